// round 1
// baseline (speedup 1.0000x reference)
#include <cuda_runtime.h>

#define HW     4096
#define CCH    256
#define BATCH  32
#define PROJ   50
#define NHEAD  5
#define LDIM   10
#define MROWS  (BATCH * CCH)       // 8192
#define FEAT   (CCH * LDIM)        // 2560
#define NSTAT  (BATCH * HW)        // 131072 elements per channel for BN

// ---------------- scratch (static device globals: no allocations) ------------
__device__ float g_P[3 * MROWS * PROJ];   // projected Q,K,V  [3][8192][50]
__device__ float g_A[MROWS * PROJ];       // post-attention   [8192][50]
__device__ float g_csum[CCH];
__device__ float g_csum2[CCH];

// =====================================================================
// K1: projection GEMM.  C[8192,50] = A[8192,4096] @ W[4096,50]
// blockIdx.y selects tensor (q/k/v). BM=64, BN=64 (padded from 50), BK=32.
// 256 threads = 16x16, each thread computes a strided 4x4 tile.
// A stored k-major in smem with stride 65 (==1 mod 32): conflict-free.
// =====================================================================
__global__ __launch_bounds__(256) void proj_kernel(
    const float* __restrict__ q, const float* __restrict__ k,
    const float* __restrict__ v,
    const float* __restrict__ wq, const float* __restrict__ wk,
    const float* __restrict__ wv)
{
    const int t = blockIdx.y;
    const float* A = (t == 0) ? q : (t == 1) ? k : v;
    const float* W = (t == 0) ? wq : (t == 1) ? wk : wv;
    float* C = g_P + (size_t)t * MROWS * PROJ;

    __shared__ float As[32][65];   // [kk][m]
    __shared__ float Bs[32][64];   // [kk][n]

    const int tid = threadIdx.x;
    const int tx = tid & 15;
    const int ty = tid >> 4;
    const int rowBase = blockIdx.x * 64;

    float acc[4][4];
#pragma unroll
    for (int i = 0; i < 4; i++)
#pragma unroll
        for (int j = 0; j < 4; j++) acc[i][j] = 0.f;

    const int kload = tid & 31;        // k within tile for A loads
    const int mload = tid >> 5;        // row group for A loads

    for (int k0 = 0; k0 < HW; k0 += 32) {
        // A tile: 64 rows x 32 k. coalesced LDG (consecutive tid -> consecutive k)
#pragma unroll
        for (int s = 0; s < 8; s++) {
            int m = mload + s * 8;
            As[kload][m] = A[(size_t)(rowBase + m) * HW + k0 + kload];
        }
        // B tile: 32 k x 64 n (zero-pad n>=50)
#pragma unroll
        for (int s = 0; s < 8; s++) {
            int idx = tid + s * 256;
            int kk = idx >> 6, n = idx & 63;
            Bs[kk][n] = (n < PROJ) ? W[(size_t)(k0 + kk) * PROJ + n] : 0.f;
        }
        __syncthreads();

#pragma unroll
        for (int kk = 0; kk < 32; kk++) {
            float a0 = As[kk][ty],      a1 = As[kk][ty + 16];
            float a2 = As[kk][ty + 32], a3 = As[kk][ty + 48];
            float b0 = Bs[kk][tx],      b1 = Bs[kk][tx + 16];
            float b2 = Bs[kk][tx + 32], b3 = Bs[kk][tx + 48];
            acc[0][0] += a0 * b0; acc[0][1] += a0 * b1; acc[0][2] += a0 * b2; acc[0][3] += a0 * b3;
            acc[1][0] += a1 * b0; acc[1][1] += a1 * b1; acc[1][2] += a1 * b2; acc[1][3] += a1 * b3;
            acc[2][0] += a2 * b0; acc[2][1] += a2 * b1; acc[2][2] += a2 * b2; acc[2][3] += a2 * b3;
            acc[3][0] += a3 * b0; acc[3][1] += a3 * b1; acc[3][2] += a3 * b2; acc[3][3] += a3 * b3;
        }
        __syncthreads();
    }

#pragma unroll
    for (int i = 0; i < 4; i++) {
        int m = rowBase + ty + 16 * i;
#pragma unroll
        for (int j = 0; j < 4; j++) {
            int n = tx + 16 * j;
            if (n < PROJ) C[(size_t)m * PROJ + n] = acc[i][j];
        }
    }
}

// =====================================================================
// K2: tiny attention per batch. 32 blocks, 256 threads (thread == channel).
//   S[i][j]  = sum_{c,l} Pq[b,c,i*10+l] * Pk[b,c,j*10+l]
//   attn     = softmax(S / sqrt(2560)) row-wise
//   A[b,c,x] = Pv[b,c,x] + sum_j attn[i][j]*Pv[b,c,j*10+l]   (x = i*10+l)
// Also zeroes the BN accumulators (block 0) ahead of K3.
// =====================================================================
__global__ __launch_bounds__(256) void attn_kernel()
{
    __shared__ float sS[NHEAD * NHEAD];
    __shared__ float sAttn[NHEAD * NHEAD];

    const int b = blockIdx.x;
    const int c = threadIdx.x;
    const int lane = threadIdx.x & 31;

    if (blockIdx.x == 0) { g_csum[c] = 0.f; g_csum2[c] = 0.f; }
    if (c < NHEAD * NHEAD) sS[c] = 0.f;
    __syncthreads();

    const size_t rowOff = (size_t)(b * CCH + c) * PROJ;
    const float* Pq = g_P + rowOff;
    const float* Pk = g_P + (size_t)MROWS * PROJ + rowOff;
    const float* Pv = g_P + 2 * (size_t)MROWS * PROJ + rowOff;

    // Gram matrix with warp reduction + smem atomics
    for (int i = 0; i < NHEAD; i++) {
        float q10[LDIM];
#pragma unroll
        for (int l = 0; l < LDIM; l++) q10[l] = Pq[i * LDIM + l];
        for (int j = 0; j < NHEAD; j++) {
            float s = 0.f;
#pragma unroll
            for (int l = 0; l < LDIM; l++) s += q10[l] * Pk[j * LDIM + l];
#pragma unroll
            for (int off = 16; off; off >>= 1)
                s += __shfl_down_sync(0xffffffffu, s, off);
            if (lane == 0) atomicAdd(&sS[i * NHEAD + j], s);
        }
    }
    __syncthreads();

    if (c < NHEAD) {
        const float inv_scale = rsqrtf((float)FEAT);
        float row[NHEAD];
        float mx = -1e30f;
#pragma unroll
        for (int j = 0; j < NHEAD; j++) {
            row[j] = sS[c * NHEAD + j] * inv_scale;
            mx = fmaxf(mx, row[j]);
        }
        float sum = 0.f;
#pragma unroll
        for (int j = 0; j < NHEAD; j++) { row[j] = __expf(row[j] - mx); sum += row[j]; }
        float rinv = 1.f / sum;
#pragma unroll
        for (int j = 0; j < NHEAD; j++) sAttn[c * NHEAD + j] = row[j] * rinv;
    }
    __syncthreads();

    // mix V with residual
    float v50[PROJ];
#pragma unroll
    for (int x = 0; x < PROJ; x++) v50[x] = Pv[x];

    float* Aout = g_A + rowOff;
#pragma unroll
    for (int i = 0; i < NHEAD; i++) {
#pragma unroll
        for (int l = 0; l < LDIM; l++) {
            float acc = v50[i * LDIM + l];
#pragma unroll
            for (int j = 0; j < NHEAD; j++)
                acc += sAttn[i * NHEAD + j] * v50[j * LDIM + l];
            Aout[i * LDIM + l] = acc;
        }
    }
}

// =====================================================================
// K3: FC GEMM + residual + BN partial stats.
//   out[m, n] = vf[m, n] + sum_k A[m,k] * Wfc[k,n]
// M=8192, K=50, N=4096. BM=64, BN=64, full K in one smem tile.
// gridDim.x = N/64 = 64, gridDim.y = M/64 = 128.
// Per-channel sums via shfl (width 16) + global atomicAdd.
// =====================================================================
__global__ __launch_bounds__(256) void fc_kernel(
    const float* __restrict__ vf, const float* __restrict__ wfc,
    float* __restrict__ out)
{
    __shared__ float As[PROJ][65];   // [k][m]
    __shared__ float Bs[PROJ][64];   // [k][n]

    const int tid = threadIdx.x;
    const int tx = tid & 15;
    const int ty = tid >> 4;
    const int rowBase = blockIdx.y * 64;
    const int colBase = blockIdx.x * 64;

    // load A tile [64 rows][50 k], k-major in smem
    for (int idx = tid; idx < 64 * PROJ; idx += 256) {
        int m = idx / PROJ, kk = idx % PROJ;
        As[kk][m] = g_A[(size_t)(rowBase + m) * PROJ + kk];
    }
    // load W tile [50 k][64 n]
    for (int idx = tid; idx < PROJ * 64; idx += 256) {
        int kk = idx >> 6, n = idx & 63;
        Bs[kk][n] = wfc[(size_t)kk * HW + colBase + n];
    }
    __syncthreads();

    float acc[4][4];
#pragma unroll
    for (int i = 0; i < 4; i++)
#pragma unroll
        for (int j = 0; j < 4; j++) acc[i][j] = 0.f;

#pragma unroll
    for (int kk = 0; kk < PROJ; kk++) {
        float a0 = As[kk][ty],      a1 = As[kk][ty + 16];
        float a2 = As[kk][ty + 32], a3 = As[kk][ty + 48];
        float b0 = Bs[kk][tx],      b1 = Bs[kk][tx + 16];
        float b2 = Bs[kk][tx + 32], b3 = Bs[kk][tx + 48];
        acc[0][0] += a0 * b0; acc[0][1] += a0 * b1; acc[0][2] += a0 * b2; acc[0][3] += a0 * b3;
        acc[1][0] += a1 * b0; acc[1][1] += a1 * b1; acc[1][2] += a1 * b2; acc[1][3] += a1 * b3;
        acc[2][0] += a2 * b0; acc[2][1] += a2 * b1; acc[2][2] += a2 * b2; acc[2][3] += a2 * b3;
        acc[3][0] += a3 * b0; acc[3][1] += a3 * b1; acc[3][2] += a3 * b2; acc[3][3] += a3 * b3;
    }

    // epilogue: residual, store, BN partial stats
#pragma unroll
    for (int i = 0; i < 4; i++) {
        int m = rowBase + ty + 16 * i;
        int chan = m & (CCH - 1);
        float sv = 0.f, sv2 = 0.f;
#pragma unroll
        for (int j = 0; j < 4; j++) {
            int n = colBase + tx + 16 * j;
            size_t idx = (size_t)m * HW + n;
            float val = acc[i][j] + vf[idx];
            out[idx] = val;
            sv += val;
            sv2 += val * val;
        }
        // reduce across the 16 tx lanes (same m)
#pragma unroll
        for (int off = 8; off; off >>= 1) {
            sv  += __shfl_down_sync(0xffffffffu, sv,  off, 16);
            sv2 += __shfl_down_sync(0xffffffffu, sv2, off, 16);
        }
        if (tx == 0) {
            atomicAdd(&g_csum[chan], sv);
            atomicAdd(&g_csum2[chan], sv2);
        }
    }
}

// =====================================================================
// K4: BatchNorm finalize, in-place on d_out. float4 per thread.
// =====================================================================
__global__ __launch_bounds__(256) void bn_kernel(
    float* __restrict__ out, const float* __restrict__ gamma,
    const float* __restrict__ beta)
{
    const int idx = blockIdx.x * blockDim.x + threadIdx.x;   // float4 index
    const int c = ((idx * 4) >> 12) & (CCH - 1);
    const float inv = 1.f / (float)NSTAT;
    float mean = g_csum[c] * inv;
    float var = g_csum2[c] * inv - mean * mean;
    float s = gamma[c] * rsqrtf(var + 1e-5f);
    float bb = beta[c] - mean * s;
    float4 x = reinterpret_cast<float4*>(out)[idx];
    x.x = x.x * s + bb;
    x.y = x.y * s + bb;
    x.z = x.z * s + bb;
    x.w = x.w * s + bb;
    reinterpret_cast<float4*>(out)[idx] = x;
}

// =====================================================================
extern "C" void kernel_launch(void* const* d_in, const int* in_sizes, int n_in,
                              void* d_out, int out_size)
{
    const float* q     = (const float*)d_in[0];
    const float* k     = (const float*)d_in[1];
    const float* v     = (const float*)d_in[2];
    const float* wq    = (const float*)d_in[3];
    const float* wk    = (const float*)d_in[4];
    const float* wv    = (const float*)d_in[5];
    const float* wfc   = (const float*)d_in[6];
    const float* gamma = (const float*)d_in[7];
    const float* beta  = (const float*)d_in[8];
    float* out = (float*)d_out;

    dim3 g1(MROWS / 64, 3);
    proj_kernel<<<g1, 256>>>(q, k, v, wq, wk, wv);

    attn_kernel<<<BATCH, 256>>>();

    dim3 g3(HW / 64, MROWS / 64);
    fc_kernel<<<g3, 256>>>(v, wfc, out);

    const int total4 = BATCH * CCH * HW / 4;
    bn_kernel<<<total4 / 256, 256>>>(out, gamma, beta);
}

// round 2
// speedup vs baseline: 1.6594x; 1.6594x over previous
#include <cuda_runtime.h>
#include <cstdint>

#define HW     4096
#define CCH    256
#define BATCH  32
#define PROJ   50
#define NHEAD  5
#define LDIM   10
#define MROWS  (BATCH * CCH)       // 8192
#define FEAT   (CCH * LDIM)        // 2560
#define NSTAT  (BATCH * HW)        // per-channel BN count

// ---------------- scratch ----------------------------------------------------
__device__ float g_P[3 * MROWS * PROJ];   // projected Q,K,V
__device__ float g_A[MROWS * PROJ];       // post-attention
__device__ float g_csum[CCH];
__device__ float g_csum2[CCH];

__device__ __forceinline__ uint32_t f2tf32(float f) {
    uint32_t u;
    asm("cvt.rna.tf32.f32 %0, %1;" : "=r"(u) : "f"(f));
    return u;
}

__device__ __forceinline__ void mma_tf32(float* d, const uint32_t* a, const uint32_t* b) {
    asm volatile(
        "mma.sync.aligned.m16n8k8.row.col.f32.tf32.tf32.f32 "
        "{%0,%1,%2,%3}, {%4,%5,%6,%7}, {%8,%9}, {%0,%1,%2,%3};"
        : "+f"(d[0]), "+f"(d[1]), "+f"(d[2]), "+f"(d[3])
        : "r"(a[0]), "r"(a[1]), "r"(a[2]), "r"(a[3]), "r"(b[0]), "r"(b[1]));
}

// =====================================================================
// K1: projection GEMM on tensor cores (tf32).
// C[8192,50] = A[8192,4096] @ W[4096,50].  BM=128, BN=64(pad), BK=32.
// smem layout [k/4][row][k%4]: fragment LDS is addr==lane mod 32 -> conflict-free.
// 8 warps: 4 in m (32 rows each), 2 in n (32 cols each). Double buffered.
// =====================================================================
__global__ __launch_bounds__(256) void proj_tc(
    const float* __restrict__ q, const float* __restrict__ k,
    const float* __restrict__ v,
    const float* __restrict__ wq, const float* __restrict__ wk,
    const float* __restrict__ wv)
{
    const int t = blockIdx.y;
    const float* A = (t == 0) ? q : (t == 1) ? k : v;
    const float* W = (t == 0) ? wq : (t == 1) ? wk : wv;
    float* C = g_P + (size_t)t * MROWS * PROJ;

    __shared__ uint32_t As[2][8][128][4];   // 32 KB
    __shared__ uint32_t Bs[2][8][64][4];    // 16 KB

    const int tid  = threadIdx.x;
    const int lane = tid & 31;
    const int warp = tid >> 5;
    const int wm   = warp & 3;
    const int wn   = warp >> 2;
    const int g    = lane >> 2;
    const int tt   = lane & 3;
    const int rowBase = blockIdx.x * 128;

    const int ma  = tid >> 1;        // A loader: row 0..127
    const int kcb = tid & 1;         // A loader: kc parity
    const int nb  = (tid >> 2) & 63; // B loader: n
    const int jb  = tid & 3;         // B loader: k%4

    float4 pa[4];
    float  pb[8];
    float  acc[2][4][4];
#pragma unroll
    for (int mt = 0; mt < 2; mt++)
#pragma unroll
        for (int nt = 0; nt < 4; nt++)
#pragma unroll
            for (int r = 0; r < 4; r++) acc[mt][nt][r] = 0.f;

    const size_t aRow = (size_t)(rowBase + ma) * HW;

    // ---- prologue: stage 0 ----
#pragma unroll
    for (int s = 0; s < 4; s++)
        pa[s] = *(const float4*)&A[aRow + (kcb + 2 * s) * 4];
#pragma unroll
    for (int ii = 0; ii < 8; ii++) {
        int kk = ii * 4 + jb;
        pb[ii] = (nb < PROJ) ? W[(size_t)kk * PROJ + nb] : 0.f;
    }
#pragma unroll
    for (int s = 0; s < 4; s++) {
        uint4 u;
        u.x = f2tf32(pa[s].x); u.y = f2tf32(pa[s].y);
        u.z = f2tf32(pa[s].z); u.w = f2tf32(pa[s].w);
        *(uint4*)&As[0][kcb + 2 * s][ma][0] = u;
    }
#pragma unroll
    for (int ii = 0; ii < 8; ii++) Bs[0][ii][nb][jb] = f2tf32(pb[ii]);
    __syncthreads();

    const int NIT = HW / 32;
    for (int it = 0; it < NIT; it++) {
        const int st = it & 1;
        // prefetch next stage into regs
        if (it + 1 < NIT) {
            const int k0 = (it + 1) * 32;
#pragma unroll
            for (int s = 0; s < 4; s++)
                pa[s] = *(const float4*)&A[aRow + k0 + (kcb + 2 * s) * 4];
#pragma unroll
            for (int ii = 0; ii < 8; ii++) {
                int kk = k0 + ii * 4 + jb;
                pb[ii] = (nb < PROJ) ? W[(size_t)kk * PROJ + nb] : 0.f;
            }
        }
        // compute current stage
#pragma unroll
        for (int ks = 0; ks < 4; ks++) {
            uint32_t af[2][4], bf[4][2];
#pragma unroll
            for (int mt = 0; mt < 2; mt++) {
                int mo = wm * 32 + mt * 16;
                af[mt][0] = As[st][ks * 2][mo + g][tt];
                af[mt][1] = As[st][ks * 2][mo + 8 + g][tt];
                af[mt][2] = As[st][ks * 2 + 1][mo + g][tt];
                af[mt][3] = As[st][ks * 2 + 1][mo + 8 + g][tt];
            }
#pragma unroll
            for (int nt = 0; nt < 4; nt++) {
                int no = wn * 32 + nt * 8;
                bf[nt][0] = Bs[st][ks * 2][no + g][tt];
                bf[nt][1] = Bs[st][ks * 2 + 1][no + g][tt];
            }
#pragma unroll
            for (int mt = 0; mt < 2; mt++)
#pragma unroll
                for (int nt = 0; nt < 4; nt++)
                    mma_tf32(acc[mt][nt], af[mt], bf[nt]);
        }
        // store next stage
        if (it + 1 < NIT) {
            const int so = st ^ 1;
#pragma unroll
            for (int s = 0; s < 4; s++) {
                uint4 u;
                u.x = f2tf32(pa[s].x); u.y = f2tf32(pa[s].y);
                u.z = f2tf32(pa[s].z); u.w = f2tf32(pa[s].w);
                *(uint4*)&As[so][kcb + 2 * s][ma][0] = u;
            }
#pragma unroll
            for (int ii = 0; ii < 8; ii++) Bs[so][ii][nb][jb] = f2tf32(pb[ii]);
            __syncthreads();
        }
    }

    // epilogue
#pragma unroll
    for (int mt = 0; mt < 2; mt++) {
        int r0 = rowBase + wm * 32 + mt * 16 + g;
#pragma unroll
        for (int nt = 0; nt < 4; nt++) {
            int c0 = wn * 32 + nt * 8 + tt * 2;
            if (c0 < PROJ) {
                C[(size_t)r0 * PROJ + c0]       = acc[mt][nt][0];
                C[(size_t)(r0 + 8) * PROJ + c0] = acc[mt][nt][2];
            }
            if (c0 + 1 < PROJ) {
                C[(size_t)r0 * PROJ + c0 + 1]       = acc[mt][nt][1];
                C[(size_t)(r0 + 8) * PROJ + c0 + 1] = acc[mt][nt][3];
            }
        }
    }
}

// =====================================================================
// K2: tiny attention per batch (unchanged). Also zeroes BN accumulators.
// =====================================================================
__global__ __launch_bounds__(256) void attn_kernel()
{
    __shared__ float sS[NHEAD * NHEAD];
    __shared__ float sAttn[NHEAD * NHEAD];

    const int b = blockIdx.x;
    const int c = threadIdx.x;
    const int lane = threadIdx.x & 31;

    if (blockIdx.x == 0) { g_csum[c] = 0.f; g_csum2[c] = 0.f; }
    if (c < NHEAD * NHEAD) sS[c] = 0.f;
    __syncthreads();

    const size_t rowOff = (size_t)(b * CCH + c) * PROJ;
    const float* Pq = g_P + rowOff;
    const float* Pk = g_P + (size_t)MROWS * PROJ + rowOff;
    const float* Pv = g_P + 2 * (size_t)MROWS * PROJ + rowOff;

    for (int i = 0; i < NHEAD; i++) {
        float q10[LDIM];
#pragma unroll
        for (int l = 0; l < LDIM; l++) q10[l] = Pq[i * LDIM + l];
        for (int j = 0; j < NHEAD; j++) {
            float s = 0.f;
#pragma unroll
            for (int l = 0; l < LDIM; l++) s += q10[l] * Pk[j * LDIM + l];
#pragma unroll
            for (int off = 16; off; off >>= 1)
                s += __shfl_down_sync(0xffffffffu, s, off);
            if (lane == 0) atomicAdd(&sS[i * NHEAD + j], s);
        }
    }
    __syncthreads();

    if (c < NHEAD) {
        const float inv_scale = rsqrtf((float)FEAT);
        float row[NHEAD];
        float mx = -1e30f;
#pragma unroll
        for (int j = 0; j < NHEAD; j++) {
            row[j] = sS[c * NHEAD + j] * inv_scale;
            mx = fmaxf(mx, row[j]);
        }
        float sum = 0.f;
#pragma unroll
        for (int j = 0; j < NHEAD; j++) { row[j] = __expf(row[j] - mx); sum += row[j]; }
        float rinv = 1.f / sum;
#pragma unroll
        for (int j = 0; j < NHEAD; j++) sAttn[c * NHEAD + j] = row[j] * rinv;
    }
    __syncthreads();

    float v50[PROJ];
#pragma unroll
    for (int x = 0; x < PROJ; x++) v50[x] = Pv[x];

    float* Aout = g_A + rowOff;
#pragma unroll
    for (int i = 0; i < NHEAD; i++) {
#pragma unroll
        for (int l = 0; l < LDIM; l++) {
            float acc = v50[i * LDIM + l];
#pragma unroll
            for (int j = 0; j < NHEAD; j++)
                acc += sAttn[i * NHEAD + j] * v50[j * LDIM + l];
            Aout[i * LDIM + l] = acc;
        }
    }
}

// =====================================================================
// K3: FC GEMM on tensor cores + residual + BN partial stats.
// out[m,n] = vf[m,n] + A[m,:50] @ Wfc[:50,n].  BM=128, BN=64, K padded to 64.
// =====================================================================
__global__ __launch_bounds__(256) void fc_tc(
    const float* __restrict__ vf, const float* __restrict__ wfc,
    float* __restrict__ out)
{
    __shared__ uint32_t As[16][128][4];   // 32 KB
    __shared__ uint32_t Bs[16][64][4];    // 16 KB

    const int tid  = threadIdx.x;
    const int lane = tid & 31;
    const int warp = tid >> 5;
    const int wm   = warp & 3;
    const int wn   = warp >> 2;
    const int g    = lane >> 2;
    const int tt   = lane & 3;
    const int rowBase = blockIdx.y * 128;
    const int colBase = blockIdx.x * 64;

    // A tile [128][64 pad]
#pragma unroll
    for (int ii = 0; ii < 32; ii++) {
        int idx = ii * 256 + tid;
        int kc = idx >> 9;
        int m  = (idx >> 2) & 127;
        int j  = idx & 3;
        int kk = kc * 4 + j;
        float vA = (kk < PROJ) ? g_A[(size_t)(rowBase + m) * PROJ + kk] : 0.f;
        As[kc][m][j] = f2tf32(vA);
    }
    // B tile [64 pad][64]
#pragma unroll
    for (int ii = 0; ii < 16; ii++) {
        int idx = ii * 256 + tid;
        int kc = idx >> 8;
        int n  = (idx >> 2) & 63;
        int j  = idx & 3;
        int kk = kc * 4 + j;
        float vB = (kk < PROJ) ? wfc[(size_t)kk * HW + colBase + n] : 0.f;
        Bs[kc][n][j] = f2tf32(vB);
    }
    __syncthreads();

    float acc[2][4][4];
#pragma unroll
    for (int mt = 0; mt < 2; mt++)
#pragma unroll
        for (int nt = 0; nt < 4; nt++)
#pragma unroll
            for (int r = 0; r < 4; r++) acc[mt][nt][r] = 0.f;

#pragma unroll
    for (int ks = 0; ks < 8; ks++) {
        uint32_t af[2][4], bf[4][2];
#pragma unroll
        for (int mt = 0; mt < 2; mt++) {
            int mo = wm * 32 + mt * 16;
            af[mt][0] = As[ks * 2][mo + g][tt];
            af[mt][1] = As[ks * 2][mo + 8 + g][tt];
            af[mt][2] = As[ks * 2 + 1][mo + g][tt];
            af[mt][3] = As[ks * 2 + 1][mo + 8 + g][tt];
        }
#pragma unroll
        for (int nt = 0; nt < 4; nt++) {
            int no = wn * 32 + nt * 8;
            bf[nt][0] = Bs[ks * 2][no + g][tt];
            bf[nt][1] = Bs[ks * 2 + 1][no + g][tt];
        }
#pragma unroll
        for (int mt = 0; mt < 2; mt++)
#pragma unroll
            for (int nt = 0; nt < 4; nt++)
                mma_tf32(acc[mt][nt], af[mt], bf[nt]);
    }

    // epilogue: residual, store, BN stats
#pragma unroll
    for (int mt = 0; mt < 2; mt++) {
        int r0 = rowBase + wm * 32 + mt * 16 + g;
        int r1 = r0 + 8;
        float s0 = 0.f, q0 = 0.f, s1 = 0.f, q1 = 0.f;
#pragma unroll
        for (int nt = 0; nt < 4; nt++) {
            int c0 = colBase + wn * 32 + nt * 8 + tt * 2;
            size_t i00 = (size_t)r0 * HW + c0;
            size_t i10 = (size_t)r1 * HW + c0;
            float v00 = acc[mt][nt][0] + vf[i00];
            float v01 = acc[mt][nt][1] + vf[i00 + 1];
            float v10 = acc[mt][nt][2] + vf[i10];
            float v11 = acc[mt][nt][3] + vf[i10 + 1];
            out[i00]     = v00;
            out[i00 + 1] = v01;
            out[i10]     = v10;
            out[i10 + 1] = v11;
            s0 += v00 + v01; q0 += v00 * v00 + v01 * v01;
            s1 += v10 + v11; q1 += v10 * v10 + v11 * v11;
        }
#pragma unroll
        for (int off = 1; off < 4; off <<= 1) {
            s0 += __shfl_xor_sync(0xffffffffu, s0, off);
            q0 += __shfl_xor_sync(0xffffffffu, q0, off);
            s1 += __shfl_xor_sync(0xffffffffu, s1, off);
            q1 += __shfl_xor_sync(0xffffffffu, q1, off);
        }
        if (tt == 0) {
            atomicAdd(&g_csum[r0 & (CCH - 1)],  s0);
            atomicAdd(&g_csum2[r0 & (CCH - 1)], q0);
            atomicAdd(&g_csum[r1 & (CCH - 1)],  s1);
            atomicAdd(&g_csum2[r1 & (CCH - 1)], q1);
        }
    }
}

// =====================================================================
// K4: BatchNorm finalize, in-place. float4 per thread.
// =====================================================================
__global__ __launch_bounds__(256) void bn_kernel(
    float* __restrict__ out, const float* __restrict__ gamma,
    const float* __restrict__ beta)
{
    const int idx = blockIdx.x * blockDim.x + threadIdx.x;
    const int c = ((idx * 4) >> 12) & (CCH - 1);
    const float inv = 1.f / (float)NSTAT;
    float mean = g_csum[c] * inv;
    float var = g_csum2[c] * inv - mean * mean;
    float s = gamma[c] * rsqrtf(var + 1e-5f);
    float bb = beta[c] - mean * s;
    float4 x = reinterpret_cast<float4*>(out)[idx];
    x.x = x.x * s + bb;
    x.y = x.y * s + bb;
    x.z = x.z * s + bb;
    x.w = x.w * s + bb;
    reinterpret_cast<float4*>(out)[idx] = x;
}

// =====================================================================
extern "C" void kernel_launch(void* const* d_in, const int* in_sizes, int n_in,
                              void* d_out, int out_size)
{
    const float* q     = (const float*)d_in[0];
    const float* k     = (const float*)d_in[1];
    const float* v     = (const float*)d_in[2];
    const float* wq    = (const float*)d_in[3];
    const float* wk    = (const float*)d_in[4];
    const float* wv    = (const float*)d_in[5];
    const float* wfc   = (const float*)d_in[6];
    const float* gamma = (const float*)d_in[7];
    const float* beta  = (const float*)d_in[8];
    float* out = (float*)d_out;

    dim3 g1(MROWS / 128, 3);
    proj_tc<<<g1, 256>>>(q, k, v, wq, wk, wv);

    attn_kernel<<<BATCH, 256>>>();

    dim3 g3(HW / 64, MROWS / 128);
    fc_tc<<<g3, 256>>>(v, wfc, out);

    const int total4 = BATCH * CCH * HW / 4;
    bn_kernel<<<total4 / 256, 256>>>(out, gamma, beta);
}

// round 3
// speedup vs baseline: 1.7370x; 1.0468x over previous
#include <cuda_runtime.h>
#include <cstdint>

#define HW     4096
#define CCH    256
#define BATCH  32
#define PROJ   50
#define NHEAD  5
#define LDIM   10
#define MROWS  (BATCH * CCH)       // 8192
#define FEAT   (CCH * LDIM)        // 2560
#define NSTAT  (BATCH * HW)

// ---------------- scratch ----------------------------------------------------
__device__ float g_P[3 * MROWS * PROJ];
__device__ float g_A[MROWS * PROJ];
__device__ float g_csum[CCH];
__device__ float g_csum2[CCH];

__device__ __forceinline__ uint32_t smem_u32(const void* p) {
    return (uint32_t)__cvta_generic_to_shared(p);
}

__device__ __forceinline__ void cp_async16(uint32_t dst, const void* src) {
    asm volatile("cp.async.cg.shared.global [%0], [%1], 16;\n" :: "r"(dst), "l"(src));
}
__device__ __forceinline__ void cp_commit() {
    asm volatile("cp.async.commit_group;\n" ::: "memory");
}
template <int N>
__device__ __forceinline__ void cp_wait() {
    asm volatile("cp.async.wait_group %0;\n" :: "n"(N) : "memory");
}

// raw fp32 bits into tf32 mma: datapath truncates to tf32 (CUTLASS fast path)
__device__ __forceinline__ void mma_tf32(float* d, const uint32_t* a, const uint32_t* b) {
    asm volatile(
        "mma.sync.aligned.m16n8k8.row.col.f32.tf32.tf32.f32 "
        "{%0,%1,%2,%3}, {%4,%5,%6,%7}, {%8,%9}, {%0,%1,%2,%3};"
        : "+f"(d[0]), "+f"(d[1]), "+f"(d[2]), "+f"(d[3])
        : "r"(a[0]), "r"(a[1]), "r"(a[2]), "r"(a[3]), "r"(b[0]), "r"(b[1]));
}

// =====================================================================
// K1: projection GEMM.  C[8192,50] = A[8192,4096] @ W[4096,50]
// BM=128, BN=64(pad), BK=32. A via 3-stage cp.async (no cvt, no reg path).
// B via LDG+STS, double-buffered. 8 warps: 4 in m x 2 in n.
// =====================================================================
__global__ __launch_bounds__(256) void proj_tc(
    const float* __restrict__ q, const float* __restrict__ k,
    const float* __restrict__ v,
    const float* __restrict__ wq, const float* __restrict__ wk,
    const float* __restrict__ wv)
{
    const int t = blockIdx.y;
    const float* A = (t == 0) ? q : (t == 1) ? k : v;
    const float* W = (t == 0) ? wq : (t == 1) ? wk : wv;
    float* C = g_P + (size_t)t * MROWS * PROJ;

    __shared__ uint32_t As[3][8][128][4];   // 48 KB, [stage][k/4][m][k%4]
    __shared__ uint32_t Bs[2][8][64][4];    // 16 KB, [stage][k/4][n][k%4]

    const int tid  = threadIdx.x;
    const int lane = tid & 31;
    const int warp = tid >> 5;
    const int wm   = warp & 3;
    const int wn   = warp >> 2;
    const int g    = lane >> 2;
    const int tt   = lane & 3;
    const int rowBase = blockIdx.x * 128;

    const int ma  = tid >> 1;        // A loader row 0..127
    const int kcb = tid & 1;         // A loader kc parity
    const int nb  = (tid >> 2) & 63; // B loader n
    const int jb  = tid & 3;         // B loader k%4

    const float* aPtr = A + (size_t)(rowBase + ma) * HW;
    uint32_t aDst[3];
#pragma unroll
    for (int s = 0; s < 3; s++) aDst[s] = smem_u32(&As[s][kcb][ma][0]);

    float acc[2][4][4];
#pragma unroll
    for (int mt = 0; mt < 2; mt++)
#pragma unroll
        for (int nt = 0; nt < 4; nt++)
#pragma unroll
            for (int r = 0; r < 4; r++) acc[mt][nt][r] = 0.f;

    float pb[8];

    // ---- prologue ----
    // A stages 0,1 via cp.async (one commit group each)
#pragma unroll
    for (int s4 = 0; s4 < 4; s4++)
        cp_async16(aDst[0] + s4 * 2 * 128 * 16, aPtr + (kcb + 2 * s4) * 4);
    cp_commit();
#pragma unroll
    for (int s4 = 0; s4 < 4; s4++)
        cp_async16(aDst[1] + s4 * 2 * 128 * 16, aPtr + 32 + (kcb + 2 * s4) * 4);
    cp_commit();

    // B stage 0 directly; prefetch regs for stage 1
#pragma unroll
    for (int ii = 0; ii < 8; ii++) {
        int kk = ii * 4 + jb;
        float vB = (nb < PROJ) ? W[(size_t)kk * PROJ + nb] : 0.f;
        Bs[0][ii][nb][jb] = __float_as_uint(vB);
    }
#pragma unroll
    for (int ii = 0; ii < 8; ii++) {
        int kk = 32 + ii * 4 + jb;
        pb[ii] = (nb < PROJ) ? W[(size_t)kk * PROJ + nb] : 0.f;
    }

    const int NIT = HW / 32;
    for (int it = 0; it < NIT; it++) {
        const int sa = it % 3;
        const int sb = it & 1;

        cp_wait<1>();          // A stage `it` landed
        __syncthreads();       // + B stage `it` visible

        // issue A stage it+2
        if (it + 2 < NIT) {
            const int so = (it + 2) % 3;
            const float* src = aPtr + (it + 2) * 32;
#pragma unroll
            for (int s4 = 0; s4 < 4; s4++)
                cp_async16(aDst[so] + s4 * 2 * 128 * 16, src + (kcb + 2 * s4) * 4);
        }
        cp_commit();           // commit every iter (possibly empty) to keep counts aligned

        // store B stage it+1 (regs prefetched last iter), prefetch B for it+2
        if (it + 1 < NIT) {
#pragma unroll
            for (int ii = 0; ii < 8; ii++)
                Bs[sb ^ 1][ii][nb][jb] = __float_as_uint(pb[ii]);
        }
        if (it + 2 < NIT) {
            const int k0 = (it + 2) * 32;
#pragma unroll
            for (int ii = 0; ii < 8; ii++) {
                int kk = k0 + ii * 4 + jb;
                pb[ii] = (nb < PROJ) ? W[(size_t)kk * PROJ + nb] : 0.f;
            }
        }

        // compute stage `it`
#pragma unroll
        for (int ks = 0; ks < 4; ks++) {
            uint32_t af[2][4], bf[4][2];
#pragma unroll
            for (int mt = 0; mt < 2; mt++) {
                int mo = wm * 32 + mt * 16;
                af[mt][0] = As[sa][ks * 2][mo + g][tt];
                af[mt][1] = As[sa][ks * 2][mo + 8 + g][tt];
                af[mt][2] = As[sa][ks * 2 + 1][mo + g][tt];
                af[mt][3] = As[sa][ks * 2 + 1][mo + 8 + g][tt];
            }
#pragma unroll
            for (int nt = 0; nt < 4; nt++) {
                int no = wn * 32 + nt * 8;
                bf[nt][0] = Bs[sb][ks * 2][no + g][tt];
                bf[nt][1] = Bs[sb][ks * 2 + 1][no + g][tt];
            }
#pragma unroll
            for (int mt = 0; mt < 2; mt++)
#pragma unroll
                for (int nt = 0; nt < 4; nt++)
                    mma_tf32(acc[mt][nt], af[mt], bf[nt]);
        }
        __syncthreads();
    }

    // epilogue: float2 stores
#pragma unroll
    for (int mt = 0; mt < 2; mt++) {
        int r0 = rowBase + wm * 32 + mt * 16 + g;
#pragma unroll
        for (int nt = 0; nt < 4; nt++) {
            int c0 = wn * 32 + nt * 8 + tt * 2;
            if (c0 + 1 < PROJ + 1 && c0 < PROJ) {
                float2 v0 = make_float2(acc[mt][nt][0], acc[mt][nt][1]);
                float2 v1 = make_float2(acc[mt][nt][2], acc[mt][nt][3]);
                *(float2*)&C[(size_t)r0 * PROJ + c0]       = v0;
                *(float2*)&C[(size_t)(r0 + 8) * PROJ + c0] = v1;
            }
        }
    }
}

// =====================================================================
// K2: tiny attention per batch. Also zeroes BN accumulators.
// =====================================================================
__global__ __launch_bounds__(256) void attn_kernel()
{
    __shared__ float sS[NHEAD * NHEAD];
    __shared__ float sAttn[NHEAD * NHEAD];

    const int b = blockIdx.x;
    const int c = threadIdx.x;
    const int lane = threadIdx.x & 31;

    if (blockIdx.x == 0) { g_csum[c] = 0.f; g_csum2[c] = 0.f; }
    if (c < NHEAD * NHEAD) sS[c] = 0.f;
    __syncthreads();

    const size_t rowOff = (size_t)(b * CCH + c) * PROJ;
    const float* Pq = g_P + rowOff;
    const float* Pk = g_P + (size_t)MROWS * PROJ + rowOff;
    const float* Pv = g_P + 2 * (size_t)MROWS * PROJ + rowOff;

    float qv[PROJ], kv[PROJ];
#pragma unroll
    for (int x = 0; x < PROJ / 2; x++) {
        float2 a = *(const float2*)&Pq[x * 2];
        float2 bq = *(const float2*)&Pk[x * 2];
        qv[x * 2] = a.x; qv[x * 2 + 1] = a.y;
        kv[x * 2] = bq.x; kv[x * 2 + 1] = bq.y;
    }

#pragma unroll
    for (int i = 0; i < NHEAD; i++) {
#pragma unroll
        for (int j = 0; j < NHEAD; j++) {
            float s = 0.f;
#pragma unroll
            for (int l = 0; l < LDIM; l++) s += qv[i * LDIM + l] * kv[j * LDIM + l];
#pragma unroll
            for (int off = 16; off; off >>= 1)
                s += __shfl_down_sync(0xffffffffu, s, off);
            if (lane == 0) atomicAdd(&sS[i * NHEAD + j], s);
        }
    }
    __syncthreads();

    if (c < NHEAD) {
        const float inv_scale = rsqrtf((float)FEAT);
        float row[NHEAD];
        float mx = -1e30f;
#pragma unroll
        for (int j = 0; j < NHEAD; j++) {
            row[j] = sS[c * NHEAD + j] * inv_scale;
            mx = fmaxf(mx, row[j]);
        }
        float sum = 0.f;
#pragma unroll
        for (int j = 0; j < NHEAD; j++) { row[j] = __expf(row[j] - mx); sum += row[j]; }
        float rinv = 1.f / sum;
#pragma unroll
        for (int j = 0; j < NHEAD; j++) sAttn[c * NHEAD + j] = row[j] * rinv;
    }
    __syncthreads();

    float v50[PROJ];
#pragma unroll
    for (int x = 0; x < PROJ / 2; x++) {
        float2 a = *(const float2*)&Pv[x * 2];
        v50[x * 2] = a.x; v50[x * 2 + 1] = a.y;
    }

    float* Aout = g_A + rowOff;
#pragma unroll
    for (int i = 0; i < NHEAD; i++) {
#pragma unroll
        for (int l = 0; l < LDIM; l += 2) {
            float a0 = v50[i * LDIM + l], a1 = v50[i * LDIM + l + 1];
#pragma unroll
            for (int j = 0; j < NHEAD; j++) {
                float w = sAttn[i * NHEAD + j];
                a0 += w * v50[j * LDIM + l];
                a1 += w * v50[j * LDIM + l + 1];
            }
            *(float2*)&Aout[i * LDIM + l] = make_float2(a0, a1);
        }
    }
}

// =====================================================================
// K3: FC GEMM + residual + BN partial stats.
// =====================================================================
__global__ __launch_bounds__(256) void fc_tc(
    const float* __restrict__ vf, const float* __restrict__ wfc,
    float* __restrict__ out)
{
    __shared__ uint32_t As[16][128][4];
    __shared__ uint32_t Bs[16][64][4];

    const int tid  = threadIdx.x;
    const int lane = tid & 31;
    const int warp = tid >> 5;
    const int wm   = warp & 3;
    const int wn   = warp >> 2;
    const int g    = lane >> 2;
    const int tt   = lane & 3;
    const int rowBase = blockIdx.y * 128;
    const int colBase = blockIdx.x * 64;

#pragma unroll
    for (int ii = 0; ii < 32; ii++) {
        int idx = ii * 256 + tid;
        int kc = idx >> 9;
        int m  = (idx >> 2) & 127;
        int j  = idx & 3;
        int kk = kc * 4 + j;
        float vA = (kk < PROJ) ? g_A[(size_t)(rowBase + m) * PROJ + kk] : 0.f;
        As[kc][m][j] = __float_as_uint(vA);
    }
#pragma unroll
    for (int ii = 0; ii < 16; ii++) {
        int idx = ii * 256 + tid;
        int kc = idx >> 8;
        int n  = (idx >> 2) & 63;
        int j  = idx & 3;
        int kk = kc * 4 + j;
        float vB = (kk < PROJ) ? wfc[(size_t)kk * HW + colBase + n] : 0.f;
        Bs[kc][n][j] = __float_as_uint(vB);
    }
    __syncthreads();

    float acc[2][4][4];
#pragma unroll
    for (int mt = 0; mt < 2; mt++)
#pragma unroll
        for (int nt = 0; nt < 4; nt++)
#pragma unroll
            for (int r = 0; r < 4; r++) acc[mt][nt][r] = 0.f;

#pragma unroll
    for (int ks = 0; ks < 8; ks++) {
        uint32_t af[2][4], bf[4][2];
#pragma unroll
        for (int mt = 0; mt < 2; mt++) {
            int mo = wm * 32 + mt * 16;
            af[mt][0] = As[ks * 2][mo + g][tt];
            af[mt][1] = As[ks * 2][mo + 8 + g][tt];
            af[mt][2] = As[ks * 2 + 1][mo + g][tt];
            af[mt][3] = As[ks * 2 + 1][mo + 8 + g][tt];
        }
#pragma unroll
        for (int nt = 0; nt < 4; nt++) {
            int no = wn * 32 + nt * 8;
            bf[nt][0] = Bs[ks * 2][no + g][tt];
            bf[nt][1] = Bs[ks * 2 + 1][no + g][tt];
        }
#pragma unroll
        for (int mt = 0; mt < 2; mt++)
#pragma unroll
            for (int nt = 0; nt < 4; nt++)
                mma_tf32(acc[mt][nt], af[mt], bf[nt]);
    }

#pragma unroll
    for (int mt = 0; mt < 2; mt++) {
        int r0 = rowBase + wm * 32 + mt * 16 + g;
        int r1 = r0 + 8;
        float s0 = 0.f, q0 = 0.f, s1 = 0.f, q1 = 0.f;
#pragma unroll
        for (int nt = 0; nt < 4; nt++) {
            int c0 = colBase + wn * 32 + nt * 8 + tt * 2;
            size_t i00 = (size_t)r0 * HW + c0;
            size_t i10 = (size_t)r1 * HW + c0;
            float2 rv0 = *(const float2*)&vf[i00];
            float2 rv1 = *(const float2*)&vf[i10];
            float v00 = acc[mt][nt][0] + rv0.x;
            float v01 = acc[mt][nt][1] + rv0.y;
            float v10 = acc[mt][nt][2] + rv1.x;
            float v11 = acc[mt][nt][3] + rv1.y;
            *(float2*)&out[i00] = make_float2(v00, v01);
            *(float2*)&out[i10] = make_float2(v10, v11);
            s0 += v00 + v01; q0 += v00 * v00 + v01 * v01;
            s1 += v10 + v11; q1 += v10 * v10 + v11 * v11;
        }
#pragma unroll
        for (int off = 1; off < 4; off <<= 1) {
            s0 += __shfl_xor_sync(0xffffffffu, s0, off);
            q0 += __shfl_xor_sync(0xffffffffu, q0, off);
            s1 += __shfl_xor_sync(0xffffffffu, s1, off);
            q1 += __shfl_xor_sync(0xffffffffu, q1, off);
        }
        if (tt == 0) {
            atomicAdd(&g_csum[r0 & (CCH - 1)],  s0);
            atomicAdd(&g_csum2[r0 & (CCH - 1)], q0);
            atomicAdd(&g_csum[r1 & (CCH - 1)],  s1);
            atomicAdd(&g_csum2[r1 & (CCH - 1)], q1);
        }
    }
}

// =====================================================================
// K4: BatchNorm finalize, in-place. float4 per thread.
// =====================================================================
__global__ __launch_bounds__(256) void bn_kernel(
    float* __restrict__ out, const float* __restrict__ gamma,
    const float* __restrict__ beta)
{
    const int idx = blockIdx.x * blockDim.x + threadIdx.x;
    const int c = ((idx * 4) >> 12) & (CCH - 1);
    const float inv = 1.f / (float)NSTAT;
    float mean = g_csum[c] * inv;
    float var = g_csum2[c] * inv - mean * mean;
    float s = gamma[c] * rsqrtf(var + 1e-5f);
    float bb = beta[c] - mean * s;
    float4 x = reinterpret_cast<float4*>(out)[idx];
    x.x = x.x * s + bb;
    x.y = x.y * s + bb;
    x.z = x.z * s + bb;
    x.w = x.w * s + bb;
    reinterpret_cast<float4*>(out)[idx] = x;
}

// =====================================================================
extern "C" void kernel_launch(void* const* d_in, const int* in_sizes, int n_in,
                              void* d_out, int out_size)
{
    const float* q     = (const float*)d_in[0];
    const float* k     = (const float*)d_in[1];
    const float* v     = (const float*)d_in[2];
    const float* wq    = (const float*)d_in[3];
    const float* wk    = (const float*)d_in[4];
    const float* wv    = (const float*)d_in[5];
    const float* wfc   = (const float*)d_in[6];
    const float* gamma = (const float*)d_in[7];
    const float* beta  = (const float*)d_in[8];
    float* out = (float*)d_out;

    dim3 g1(MROWS / 128, 3);
    proj_tc<<<g1, 256>>>(q, k, v, wq, wk, wv);

    attn_kernel<<<BATCH, 256>>>();

    dim3 g3(HW / 64, MROWS / 128);
    fc_tc<<<g3, 256>>>(v, wfc, out);

    const int total4 = BATCH * CCH * HW / 4;
    bn_kernel<<<total4 / 256, 256>>>(out, gamma, beta);
}

// round 5
// speedup vs baseline: 2.6052x; 1.4998x over previous
#include <cuda_runtime.h>
#include <cstdint>

#define HW     4096
#define CCH    256
#define BATCH  32
#define PROJ   50
#define NHEAD  5
#define LDIM   10
#define MROWS  (BATCH * CCH)       // 8192
#define FEAT   (CCH * LDIM)        // 2560
#define NSTAT  (BATCH * HW)

// ---------------- scratch ----------------------------------------------------
__device__ float g_P[3 * MROWS * PROJ];
__device__ float g_A[MROWS * PROJ];
__device__ float g_csum[CCH];
__device__ float g_csum2[CCH];

// pack two fp32 into bf16x2 (lo = first k, hi = second k), round-to-nearest
__device__ __forceinline__ uint32_t pack_bf16(float lo, float hi) {
    uint32_t d;
    asm("cvt.rn.bf16x2.f32 %0, %1, %2;" : "=r"(d) : "f"(hi), "f"(lo));
    return d;
}

__device__ __forceinline__ void mma_bf16(float* d, const uint32_t* a, const uint32_t* b) {
    asm volatile(
        "mma.sync.aligned.m16n8k16.row.col.f32.bf16.bf16.f32 "
        "{%0,%1,%2,%3}, {%4,%5,%6,%7}, {%8,%9}, {%0,%1,%2,%3};"
        : "+f"(d[0]), "+f"(d[1]), "+f"(d[2]), "+f"(d[3])
        : "r"(a[0]), "r"(a[1]), "r"(a[2]), "r"(a[3]), "r"(b[0]), "r"(b[1]));
}

// =====================================================================
// K1: projection GEMM, bf16 HMMA.  C[8192,50] = A[8192,4096] @ W[4096,50]
// BM=128, BN=64(pad), BK=32. smem holds packed bf16 pairs:
// As[stage][p4][m][pj] where k = p4*8 + pj*2 (+0/1 in the word).
// Fragment LDS: addr word = m*4 + tt (mod 32 distinct) -> conflict-free.
// Register double-buffer; 1 barrier/iter. 8 warps: 4 in m x 2 in n.
// =====================================================================
__global__ __launch_bounds__(256, 2) void proj_tc(
    const float* __restrict__ q, const float* __restrict__ k,
    const float* __restrict__ v,
    const float* __restrict__ wq, const float* __restrict__ wk,
    const float* __restrict__ wv)
{
    const int t = blockIdx.y;
    const float* A = (t == 0) ? q : (t == 1) ? k : v;
    const float* W = (t == 0) ? wq : (t == 1) ? wk : wv;
    float* C = g_P + (size_t)t * MROWS * PROJ;

    __shared__ uint32_t As[2][4][128][4];   // 16 KB
    __shared__ uint32_t Bs[2][4][64][4];    //  8 KB

    const int tid  = threadIdx.x;
    const int lane = tid & 31;
    const int warp = tid >> 5;
    const int wm   = warp & 3;
    const int wn   = warp >> 2;
    const int g    = lane >> 2;
    const int tt   = lane & 3;
    const int rowBase = blockIdx.x * 128;

    // A loader: row ma, k-half
    const int ma   = tid >> 1;
    const int half = tid & 1;
    // B loader: column n, k-octet wsel
    const int nb   = tid & 63;
    const int wsel = tid >> 6;

    const float* aPtr = A + (size_t)(rowBase + ma) * HW + half * 16;

    float4 pa[4];
    float  pb[8];
    float  acc[2][4][4];
#pragma unroll
    for (int mt = 0; mt < 2; mt++)
#pragma unroll
        for (int nt = 0; nt < 4; nt++)
#pragma unroll
            for (int r = 0; r < 4; r++) acc[mt][nt][r] = 0.f;

#define LOAD_REGS(K0)                                                        \
    do {                                                                     \
        _Pragma("unroll")                                                    \
        for (int s4 = 0; s4 < 4; s4++)                                       \
            pa[s4] = *(const float4*)&aPtr[(K0) + s4 * 4];                   \
        _Pragma("unroll")                                                    \
        for (int j = 0; j < 8; j++) {                                        \
            int kk = (K0) + wsel * 8 + j;                                    \
            pb[j] = (nb < PROJ) ? W[(size_t)kk * PROJ + nb] : 0.f;           \
        }                                                                    \
    } while (0)

#define STORE_SMEM(ST)                                                       \
    do {                                                                     \
        _Pragma("unroll")                                                    \
        for (int s4 = 0; s4 < 4; s4++) {                                     \
            int p4 = half * 2 + (s4 >> 1);                                   \
            int pj = (s4 & 1) * 2;                                           \
            uint2 u;                                                         \
            u.x = pack_bf16(pa[s4].x, pa[s4].y);                             \
            u.y = pack_bf16(pa[s4].z, pa[s4].w);                             \
            *(uint2*)&As[ST][p4][ma][pj] = u;                                \
        }                                                                    \
        _Pragma("unroll")                                                    \
        for (int pj = 0; pj < 4; pj++)                                       \
            Bs[ST][wsel][nb][pj] = pack_bf16(pb[2 * pj], pb[2 * pj + 1]);    \
    } while (0)

    // prologue
    LOAD_REGS(0);
    STORE_SMEM(0);
    LOAD_REGS(32);
    __syncthreads();

    const int NIT = HW / 32;
    for (int it = 0; it < NIT; it++) {
        const int st = it & 1;
        if (it + 1 < NIT) STORE_SMEM(st ^ 1);
        if (it + 2 < NIT) LOAD_REGS((it + 2) * 32);

        // compute stage st: two k16 steps
#pragma unroll
        for (int ck = 0; ck < 2; ck++) {
            uint32_t af[2][4], bf[4][2];
#pragma unroll
            for (int mt = 0; mt < 2; mt++) {
                int mo = wm * 32 + mt * 16;
                af[mt][0] = As[st][ck * 2][mo + g][tt];
                af[mt][1] = As[st][ck * 2][mo + 8 + g][tt];
                af[mt][2] = As[st][ck * 2 + 1][mo + g][tt];
                af[mt][3] = As[st][ck * 2 + 1][mo + 8 + g][tt];
            }
#pragma unroll
            for (int nt = 0; nt < 4; nt++) {
                int no = wn * 32 + nt * 8;
                bf[nt][0] = Bs[st][ck * 2][no + g][tt];
                bf[nt][1] = Bs[st][ck * 2 + 1][no + g][tt];
            }
#pragma unroll
            for (int mt = 0; mt < 2; mt++)
#pragma unroll
                for (int nt = 0; nt < 4; nt++)
                    mma_bf16(acc[mt][nt], af[mt], bf[nt]);
        }
        __syncthreads();
    }
#undef LOAD_REGS
#undef STORE_SMEM

    // epilogue
#pragma unroll
    for (int mt = 0; mt < 2; mt++) {
        int r0 = rowBase + wm * 32 + mt * 16 + g;
#pragma unroll
        for (int nt = 0; nt < 4; nt++) {
            int c0 = wn * 32 + nt * 8 + tt * 2;
            if (c0 < PROJ) {
                *(float2*)&C[(size_t)r0 * PROJ + c0] =
                    make_float2(acc[mt][nt][0], acc[mt][nt][1]);
                *(float2*)&C[(size_t)(r0 + 8) * PROJ + c0] =
                    make_float2(acc[mt][nt][2], acc[mt][nt][3]);
            }
        }
    }
}

// =====================================================================
// K2: tiny attention per batch. Also zeroes BN accumulators.
// =====================================================================
__global__ __launch_bounds__(256) void attn_kernel()
{
    __shared__ float sS[NHEAD * NHEAD];
    __shared__ float sAttn[NHEAD * NHEAD];

    const int b = blockIdx.x;
    const int c = threadIdx.x;
    const int lane = threadIdx.x & 31;

    if (blockIdx.x == 0) { g_csum[c] = 0.f; g_csum2[c] = 0.f; }
    if (c < NHEAD * NHEAD) sS[c] = 0.f;
    __syncthreads();

    const size_t rowOff = (size_t)(b * CCH + c) * PROJ;
    const float* Pq = g_P + rowOff;
    const float* Pk = g_P + (size_t)MROWS * PROJ + rowOff;
    const float* Pv = g_P + 2 * (size_t)MROWS * PROJ + rowOff;

    float qv[PROJ], kv[PROJ];
#pragma unroll
    for (int x = 0; x < PROJ / 2; x++) {
        float2 a = *(const float2*)&Pq[x * 2];
        float2 bq = *(const float2*)&Pk[x * 2];
        qv[x * 2] = a.x; qv[x * 2 + 1] = a.y;
        kv[x * 2] = bq.x; kv[x * 2 + 1] = bq.y;
    }

#pragma unroll
    for (int i = 0; i < NHEAD; i++) {
#pragma unroll
        for (int j = 0; j < NHEAD; j++) {
            float s = 0.f;
#pragma unroll
            for (int l = 0; l < LDIM; l++) s += qv[i * LDIM + l] * kv[j * LDIM + l];
#pragma unroll
            for (int off = 16; off; off >>= 1)
                s += __shfl_down_sync(0xffffffffu, s, off);
            if (lane == 0) atomicAdd(&sS[i * NHEAD + j], s);
        }
    }
    __syncthreads();

    if (c < NHEAD) {
        const float inv_scale = rsqrtf((float)FEAT);
        float row[NHEAD];
        float mx = -1e30f;
#pragma unroll
        for (int j = 0; j < NHEAD; j++) {
            row[j] = sS[c * NHEAD + j] * inv_scale;
            mx = fmaxf(mx, row[j]);
        }
        float sum = 0.f;
#pragma unroll
        for (int j = 0; j < NHEAD; j++) { row[j] = __expf(row[j] - mx); sum += row[j]; }
        float rinv = 1.f / sum;
#pragma unroll
        for (int j = 0; j < NHEAD; j++) sAttn[c * NHEAD + j] = row[j] * rinv;
    }
    __syncthreads();

    float v50[PROJ];
#pragma unroll
    for (int x = 0; x < PROJ / 2; x++) {
        float2 a = *(const float2*)&Pv[x * 2];
        v50[x * 2] = a.x; v50[x * 2 + 1] = a.y;
    }

    float* Aout = g_A + rowOff;
#pragma unroll
    for (int i = 0; i < NHEAD; i++) {
#pragma unroll
        for (int l = 0; l < LDIM; l += 2) {
            float a0 = v50[i * LDIM + l], a1 = v50[i * LDIM + l + 1];
#pragma unroll
            for (int j = 0; j < NHEAD; j++) {
                float w = sAttn[i * NHEAD + j];
                a0 += w * v50[j * LDIM + l];
                a1 += w * v50[j * LDIM + l + 1];
            }
            *(float2*)&Aout[i * LDIM + l] = make_float2(a0, a1);
        }
    }
}

// =====================================================================
// K3: FC GEMM (bf16 HMMA) + residual + BN partial stats.
// out[m,n] = vf[m,n] + A[m,:50] @ Wfc[:50,n].  BM=128, BN=64, K pad 64.
// =====================================================================
__global__ __launch_bounds__(256) void fc_tc(
    const float* __restrict__ vf, const float* __restrict__ wfc,
    float* __restrict__ out)
{
    __shared__ uint32_t As[8][128][4];   // 16 KB, k = p4*8 + pj*2
    __shared__ uint32_t Bs[8][64][4];    //  8 KB

    const int tid  = threadIdx.x;
    const int lane = tid & 31;
    const int warp = tid >> 5;
    const int wm   = warp & 3;
    const int wn   = warp >> 2;
    const int g    = lane >> 2;
    const int tt   = lane & 3;
    const int rowBase = blockIdx.y * 128;
    const int colBase = blockIdx.x * 64;

    // A tile: 8*128*4 = 4096 words
#pragma unroll
    for (int ii = 0; ii < 16; ii++) {
        int widx = ii * 256 + tid;
        int p4 = widx >> 9;
        int m  = (widx >> 2) & 127;
        int pj = widx & 3;
        int kk = p4 * 8 + pj * 2;
        const float* src = &g_A[(size_t)(rowBase + m) * PROJ + kk];
        float v0 = (kk < PROJ) ? src[0] : 0.f;
        float v1 = (kk + 1 < PROJ) ? src[1] : 0.f;
        As[p4][m][pj] = pack_bf16(v0, v1);
    }
    // B tile: 8*64*4 = 2048 words
#pragma unroll
    for (int ii = 0; ii < 8; ii++) {
        int widx = ii * 256 + tid;
        int p4 = widx >> 8;
        int n  = (widx >> 2) & 63;
        int pj = widx & 3;
        int kk = p4 * 8 + pj * 2;
        float v0 = (kk < PROJ) ? wfc[(size_t)kk * HW + colBase + n] : 0.f;
        float v1 = (kk + 1 < PROJ) ? wfc[(size_t)(kk + 1) * HW + colBase + n] : 0.f;
        Bs[p4][n][pj] = pack_bf16(v0, v1);
    }
    __syncthreads();

    float acc[2][4][4];
#pragma unroll
    for (int mt = 0; mt < 2; mt++)
#pragma unroll
        for (int nt = 0; nt < 4; nt++)
#pragma unroll
            for (int r = 0; r < 4; r++) acc[mt][nt][r] = 0.f;

#pragma unroll
    for (int ck = 0; ck < 4; ck++) {
        uint32_t af[2][4], bf[4][2];
#pragma unroll
        for (int mt = 0; mt < 2; mt++) {
            int mo = wm * 32 + mt * 16;
            af[mt][0] = As[ck * 2][mo + g][tt];
            af[mt][1] = As[ck * 2][mo + 8 + g][tt];
            af[mt][2] = As[ck * 2 + 1][mo + g][tt];
            af[mt][3] = As[ck * 2 + 1][mo + 8 + g][tt];
        }
#pragma unroll
        for (int nt = 0; nt < 4; nt++) {
            int no = wn * 32 + nt * 8;
            bf[nt][0] = Bs[ck * 2][no + g][tt];
            bf[nt][1] = Bs[ck * 2 + 1][no + g][tt];
        }
#pragma unroll
        for (int mt = 0; mt < 2; mt++)
#pragma unroll
            for (int nt = 0; nt < 4; nt++)
                mma_bf16(acc[mt][nt], af[mt], bf[nt]);
    }

#pragma unroll
    for (int mt = 0; mt < 2; mt++) {
        int r0 = rowBase + wm * 32 + mt * 16 + g;
        int r1 = r0 + 8;
        float s0 = 0.f, q0 = 0.f, s1 = 0.f, q1 = 0.f;
#pragma unroll
        for (int nt = 0; nt < 4; nt++) {
            int c0 = colBase + wn * 32 + nt * 8 + tt * 2;
            size_t i00 = (size_t)r0 * HW + c0;
            size_t i10 = (size_t)r1 * HW + c0;
            float2 rv0 = *(const float2*)&vf[i00];
            float2 rv1 = *(const float2*)&vf[i10];
            float v00 = acc[mt][nt][0] + rv0.x;
            float v01 = acc[mt][nt][1] + rv0.y;
            float v10 = acc[mt][nt][2] + rv1.x;
            float v11 = acc[mt][nt][3] + rv1.y;
            *(float2*)&out[i00] = make_float2(v00, v01);
            *(float2*)&out[i10] = make_float2(v10, v11);
            s0 += v00 + v01; q0 += v00 * v00 + v01 * v01;
            s1 += v10 + v11; q1 += v10 * v10 + v11 * v11;
        }
#pragma unroll
        for (int off = 1; off < 4; off <<= 1) {
            s0 += __shfl_xor_sync(0xffffffffu, s0, off);
            q0 += __shfl_xor_sync(0xffffffffu, q0, off);
            s1 += __shfl_xor_sync(0xffffffffu, s1, off);
            q1 += __shfl_xor_sync(0xffffffffu, q1, off);
        }
        if (tt == 0) {
            atomicAdd(&g_csum[r0 & (CCH - 1)],  s0);
            atomicAdd(&g_csum2[r0 & (CCH - 1)], q0);
            atomicAdd(&g_csum[r1 & (CCH - 1)],  s1);
            atomicAdd(&g_csum2[r1 & (CCH - 1)], q1);
        }
    }
}

// =====================================================================
// K4: BatchNorm finalize, in-place. float4 per thread.
// =====================================================================
__global__ __launch_bounds__(256) void bn_kernel(
    float* __restrict__ out, const float* __restrict__ gamma,
    const float* __restrict__ beta)
{
    const int idx = blockIdx.x * blockDim.x + threadIdx.x;
    const int c = ((idx * 4) >> 12) & (CCH - 1);
    const float inv = 1.f / (float)NSTAT;
    float mean = g_csum[c] * inv;
    float var = g_csum2[c] * inv - mean * mean;
    float s = gamma[c] * rsqrtf(var + 1e-5f);
    float bb = beta[c] - mean * s;
    float4 x = reinterpret_cast<float4*>(out)[idx];
    x.x = x.x * s + bb;
    x.y = x.y * s + bb;
    x.z = x.z * s + bb;
    x.w = x.w * s + bb;
    reinterpret_cast<float4*>(out)[idx] = x;
}

// =====================================================================
extern "C" void kernel_launch(void* const* d_in, const int* in_sizes, int n_in,
                              void* d_out, int out_size)
{
    const float* q     = (const float*)d_in[0];
    const float* k     = (const float*)d_in[1];
    const float* v     = (const float*)d_in[2];
    const float* wq    = (const float*)d_in[3];
    const float* wk    = (const float*)d_in[4];
    const float* wv    = (const float*)d_in[5];
    const float* wfc   = (const float*)d_in[6];
    const float* gamma = (const float*)d_in[7];
    const float* beta  = (const float*)d_in[8];
    float* out = (float*)d_out;

    dim3 g1(MROWS / 128, 3);
    proj_tc<<<g1, 256>>>(q, k, v, wq, wk, wv);

    attn_kernel<<<BATCH, 256>>>();

    dim3 g3(HW / 64, MROWS / 128);
    fc_tc<<<g3, 256>>>(v, wfc, out);

    const int total4 = BATCH * CCH * HW / 4;
    bn_kernel<<<total4 / 256, 256>>>(out, gamma, beta);
}